// round 11
// baseline (speedup 1.0000x reference)
#include <cuda_runtime.h>
#include <math.h>

#define NMAX   16384
#define KNN    11            // neighbors kept (K=12 graph minus self)
#define G      48            // grid cells per dim
#define NC     (G * G * G)   // 110592 cells
#define SCAN_B 256
#define NB1    (NC / SCAN_B) // 432
#define XMIN   (-4.8f)
#define H      0.2f
#define INVH   5.0f
#define RADCAP2 2.25f        // max seed (d^2 units), rad <= 1.5
#define QW     4             // warps (queries) per block
#define CCAND  176           // per-warp candidate buffer (704 floats = repair scratch)

// Static device scratch (no allocations allowed).
__device__ float4 g_pk[NMAX];        // original-order points
__device__ int    g_cnt[NC];         // per-cell counts
__device__ int    g_cexc[NC];        // within-chunk exclusive scan
__device__ int    g_bsum[NB1];       // chunk sums
__device__ int    g_cstart[NC + 1];  // CSR starts + sentinel
__device__ int    g_qcell[NMAX];
__device__ int    g_qslot[NMAX];
__device__ float4 g_spts[NMAX];      // cell-sorted points: x,y,z,bitcast(idx)

__global__ void zero_kernel() {
    int i = blockIdx.x * blockDim.x + threadIdx.x;
    int4* p = (int4*)g_cnt;
    if (i < NC / 4) p[i] = make_int4(0, 0, 0, 0);
}

__global__ void bin_kernel(const float* __restrict__ p, int n) {
    int i = blockIdx.x * blockDim.x + threadIdx.x;
    if (i >= n) return;
    float x = p[3 * i + 0];
    float y = p[3 * i + 1];
    float z = p[3 * i + 2];
    g_pk[i] = make_float4(x, y, z, 0.0f);

    int ix = min(max((int)floorf((x - XMIN) * INVH), 0), G - 1);
    int iy = min(max((int)floorf((y - XMIN) * INVH), 0), G - 1);
    int iz = min(max((int)floorf((z - XMIN) * INVH), 0), G - 1);
    int cell = (iz * G + iy) * G + ix;

    g_qcell[i] = cell;
    g_qslot[i] = atomicAdd(&g_cnt[cell], 1);
}

// Warp-shuffle block scan over 256 cells; writes within-chunk exclusive
// prefix and the chunk total.
__global__ void scan1_kernel() {
    __shared__ int wsum[8];
    int b = blockIdx.x, t = threadIdx.x;
    int lane = t & 31, w = t >> 5;
    int i = b * SCAN_B + t;
    int v = g_cnt[i];
    int x = v;
#pragma unroll
    for (int o = 1; o < 32; o <<= 1) {
        int y = __shfl_up_sync(0xffffffffu, x, o);
        if (lane >= o) x += y;
    }
    if (lane == 31) wsum[w] = x;
    __syncthreads();
    if (w == 0) {
        int s = (lane < 8) ? wsum[lane] : 0;
#pragma unroll
        for (int o = 1; o < 8; o <<= 1) {
            int y = __shfl_up_sync(0xffffffffu, s, o);
            if (lane >= o) s += y;
        }
        if (lane < 8) wsum[lane] = s;
    }
    __syncthreads();
    int off = (w > 0) ? wsum[w - 1] : 0;
    g_cexc[i] = off + x - v;
    if (t == SCAN_B - 1) g_bsum[b] = off + x;
}

// finalize: block b needs only sum(bsum[0..b-1]) — warp 0 computes it
// directly (<=14 loads/lane), then all threads write their cstart entries.
__global__ void finalize_kernel(int n) {
    __shared__ int s_off;
    int b = blockIdx.x, t = threadIdx.x;
    if (t < 32) {
        int acc = 0;
        for (int i = t; i < b; i += 32) acc += g_bsum[i];
#pragma unroll
        for (int o = 16; o > 0; o >>= 1)
            acc += __shfl_xor_sync(0xffffffffu, acc, o);
        if (t == 0) s_off = acc;
    }
    __syncthreads();
    int i = b * SCAN_B + t;
    g_cstart[i] = s_off + g_cexc[i];
    if (i == NC - 1) g_cstart[NC] = n;
}

__global__ void scatter_kernel(int n) {
    int i = blockIdx.x * blockDim.x + threadIdx.x;
    if (i >= n) return;
    int pos = g_cstart[g_qcell[i]] + g_qslot[i];
    float4 pk = g_pk[i];
    g_spts[pos] = make_float4(pk.x, pk.y, pk.z, __int_as_float(i));
}

// Warp-per-query grid search + fused exact repair.
// Lanes set up row slices in parallel; nonempty rows are ballot-masked;
// in-ball hits ballot-compact into smem; top-11 by rank counting.
// On failure (undercount/overflow — warp-uniform) the warp brute-forces
// its own query using the smem candidate buffer as list scratch.
__global__ __launch_bounds__(QW * 32) void query_kernel(
    const float* __restrict__ W,
    const float* __restrict__ Bb,
    float* __restrict__ out,
    int n)
{
    __shared__ float4 s_cand[QW][CCAND];   // 704 floats/warp (repair scratch)
    __shared__ float  s_d[QW][CCAND];

    int warp = threadIdx.x >> 5;
    int lane = threadIdx.x & 31;
    int t = blockIdx.x * QW + warp;
    if (t >= n) return;

    float4 me = g_spts[t];
    float qx = me.x, qy = me.y, qz = me.z;
    int   qi = __float_as_int(me.w);

    float w0 = W[0], w1 = W[1], w2 = W[2];
    float bias = Bb[0];
    const float inv_s2 = 0.7071067811865475f;
    const float c0f = (1.0f + (float)KNN * inv_s2) / 12.0f; // (1+11/sqrt2)/12
    const float c1f = 1.0f / 24.0f;                          // 0.5/12

    // Analytic seed threshold (11-NN radius from local Gaussian density).
    float q2 = qx * qx + qy * qy + qz * qz;
    float lam = (float)n * 0.063493636f * __expf(-0.5f * q2);
    float f = 2.6260608f / lam;
    float r2 = cbrtf(f * f);
    float seed = fminf((2.0f + 0.25f * q2) * r2, RADCAP2);
    float rad = sqrtf(seed);

    int y0 = min(max((int)floorf((qy - rad - XMIN) * INVH), 0), G - 1);
    int y1 = min(max((int)floorf((qy + rad - XMIN) * INVH), 0), G - 1);
    int z0 = min(max((int)floorf((qz - rad - XMIN) * INVH), 0), G - 1);
    int z1 = min(max((int)floorf((qz + rad - XMIN) * INVH), 0), G - 1);
    int nry = y1 - y0 + 1;
    int nrows = nry * (z1 - z0 + 1);

    int cnt = 0;

    for (int rb = 0; rb < nrows; rb += 32) {
        int r = rb + lane;
        bool valid = r < nrows;
        int st = 0, en = 0;
        if (valid) {
            int iz = z0 + r / nry;
            int iy = y0 + r % nry;
            float ylo = XMIN + iy * H;
            float zlo = XMIN + iz * H;
            float dy = fmaxf(fmaxf(ylo - qy, qy - (ylo + H)), 0.0f);
            float dz = fmaxf(fmaxf(zlo - qz, qz - (zlo + H)), 0.0f);
            float rem = seed - dy * dy - dz * dz;
            if (rem > 0.0f) {
                float hw = sqrtf(rem);
                int x0 = min(max((int)floorf((qx - hw - XMIN) * INVH), 0), G - 1);
                int x1 = min(max((int)floorf((qx + hw - XMIN) * INVH), 0), G - 1);
                int base = (iz * G + iy) * G;
                st = g_cstart[base + x0];
                en = g_cstart[base + x1 + 1];
            }
        }
        unsigned rowmask = __ballot_sync(0xffffffffu, en > st);
        while (rowmask) {
            int rr = __ffs(rowmask) - 1;
            rowmask &= rowmask - 1;
            int rst = __shfl_sync(0xffffffffu, st, rr);
            int ren = __shfl_sync(0xffffffffu, en, rr);
            for (int cb = rst; cb < ren; cb += 32) {
                int c = cb + lane;
                bool act = c < ren;
                float4 cd = act ? g_spts[c]
                                : make_float4(0.f, 0.f, 0.f, __int_as_float(-1));
                float dx = qx - cd.x;
                float dy = qy - cd.y;
                float dz = qz - cd.z;
                float d = fmaf(dz, dz, fmaf(dy, dy, dx * dx));
                bool keep = act && (d < seed) && (__float_as_int(cd.w) != qi);
                unsigned m = __ballot_sync(0xffffffffu, keep);
                int pos = cnt + __popc(m & ((1u << lane) - 1u));
                if (keep && pos < CCAND) {
                    s_cand[warp][pos] = cd;
                    s_d[warp][pos] = d;
                }
                cnt += __popc(m);
            }
        }
    }

    __syncwarp();

    if (cnt >= KNN && cnt <= CCAND) {
        // Rank selection: item i is a neighbor iff fewer than KNN items
        // are strictly smaller (ties by index). Sum is order-invariant.
        float Ssum = 0.0f;
        for (int i = lane; i < cnt; i += 32) {
            float di = s_d[warp][i];
            int rank = 0;
            for (int j = 0; j < cnt; j++) {
                float dj = s_d[warp][j];
                rank += (dj < di) || (dj == di && j < i);
            }
            if (rank < KNN) {
                float4 cd = s_cand[warp][i];
                Ssum += fabsf(qx - cd.x) * w0 + fabsf(qy - cd.y) * w1
                      + fabsf(qz - cd.z) * w2;
            }
        }
#pragma unroll
        for (int o = 16; o > 0; o >>= 1)
            Ssum += __shfl_xor_sync(0xffffffffu, Ssum, o);

        if (lane == 0) {
            float xw0 = qx * w0 + qy * w1 + qz * w2;
            out[qi] = fmaf(c0f, xw0, fmaf(c1f, Ssum, bias));
        }
        return;
    }

    // ---- Fused exact repair (warp-uniform path) ----
    // Per-lane sorted top-11 lists live in the candidate buffer:
    // dist in floats [0..351], idx in [352..703].
    float* dl = (float*)&s_cand[warp][0];
    int*   il = (int*)(dl + 32 * KNN);

#pragma unroll
    for (int k = 0; k < KNN; k++) {
        dl[lane * KNN + k] = 3.0e38f;
        il[lane * KNN + k] = -1;
    }
    __syncwarp();

    for (int c = lane; c < n; c += 32) {
        float4 cd = g_spts[c];
        float dx = qx - cd.x;
        float dy = qy - cd.y;
        float dz = qz - cd.z;
        float d = fmaf(dz, dz, fmaf(dy, dy, dx * dx));
        int j = __float_as_int(cd.w);
        if (j != qi && d < dl[lane * KNN + KNN - 1]) {
            float dd = d; int jj = j;
#pragma unroll
            for (int k = 0; k < KNN; k++) {
                float cur = dl[lane * KNN + k];
                if (dd < cur) {
                    int ci = il[lane * KNN + k];
                    dl[lane * KNN + k] = dd; il[lane * KNN + k] = jj;
                    dd = cur; jj = ci;
                }
            }
        }
    }
    __syncwarp();

    // Tournament merge: 5 levels; reader folds partner's sorted list
    // (partner is inactive at this level, so its region is stable).
    for (int stride = 16; stride >= 1; stride >>= 1) {
        if (lane < stride) {
            int pr = (lane + stride) * KNN;
#pragma unroll
            for (int k = 0; k < KNN; k++) {
                float d = dl[pr + k];
                if (d >= dl[lane * KNN + KNN - 1]) break;
                int j = il[pr + k];
                if (j < 0) break;
                float dd = d; int jj = j;
#pragma unroll
                for (int m = 0; m < KNN; m++) {
                    float cur = dl[lane * KNN + m];
                    if (dd < cur) {
                        int ci = il[lane * KNN + m];
                        dl[lane * KNN + m] = dd; il[lane * KNN + m] = jj;
                        dd = cur; jj = ci;
                    }
                }
            }
        }
        __syncwarp();
    }

    float Ssum = 0.0f;
    if (lane < KNN) {
        float4 c = g_pk[il[lane]];   // lane 0's final list
        Ssum = fabsf(qx - c.x) * w0 + fabsf(qy - c.y) * w1
             + fabsf(qz - c.z) * w2;
    }
#pragma unroll
    for (int o = 16; o > 0; o >>= 1)
        Ssum += __shfl_xor_sync(0xffffffffu, Ssum, o);

    if (lane == 0) {
        float xw0 = qx * w0 + qy * w1 + qz * w2;
        out[qi] = fmaf(c0f, xw0, fmaf(c1f, Ssum, bias));
    }
}

extern "C" void kernel_launch(void* const* d_in, const int* in_sizes, int n_in,
                              void* d_out, int out_size) {
    const float* p = (const float*)d_in[0];   // [2*8192*3] fp32
    const float* W = (const float*)d_in[1];   // [3]
    const float* b = (const float*)d_in[2];   // [1]
    float* out = (float*)d_out;               // [n,1] fp32

    int n = in_sizes[0] / 3;                  // 16384

    zero_kernel<<<(NC / 4 + 255) / 256, 256>>>();
    bin_kernel<<<(n + 255) / 256, 256>>>(p, n);
    scan1_kernel<<<NB1, SCAN_B>>>();
    finalize_kernel<<<NB1, SCAN_B>>>(n);
    scatter_kernel<<<(n + 255) / 256, 256>>>(n);
    query_kernel<<<(n + QW - 1) / QW, QW * 32>>>(W, b, out, n);
}

// round 12
// speedup vs baseline: 2.0786x; 2.0786x over previous
#include <cuda_runtime.h>
#include <math.h>

#define NMAX   16384
#define KNN    11            // neighbors kept (K=12 graph minus self)
#define G      32            // grid cells per dim
#define NC     (G * G * G)   // 32768 cells
#define SCAN_B 256
#define NB1    (NC / SCAN_B) // 128
#define XMIN   (-4.8f)
#define H      0.3f
#define INVH   3.3333333333f
#define RADCAP2 2.25f        // max seed (d^2 units), rad <= 1.5
#define QW     4             // warps (queries) per block
#define CCAND  160           // per-warp candidate buffer
#define RTPB   256
#define RGRID  2048

// Static device scratch (no allocations allowed).
__device__ float4 g_pk[NMAX];        // original-order points
__device__ int    g_cnt[NC];         // per-cell counts
__device__ int    g_cexc[NC];        // within-chunk exclusive scan
__device__ int    g_bsum[NB1];       // chunk sums
__device__ int    g_cstart[NC + 1];  // CSR starts + sentinel
__device__ int    g_qcell[NMAX];
__device__ int    g_qslot[NMAX];
__device__ float4 g_spts[NMAX];      // cell-sorted points: x,y,z,bitcast(idx)
__device__ int    g_fail_cnt;
__device__ int    g_fail[NMAX];

__global__ void zero_kernel() {
    int i = blockIdx.x * blockDim.x + threadIdx.x;
    int4* p = (int4*)g_cnt;
    if (i < NC / 4) p[i] = make_int4(0, 0, 0, 0);
    if (i == 0) g_fail_cnt = 0;
}

__global__ void bin_kernel(const float* __restrict__ p, int n) {
    int i = blockIdx.x * blockDim.x + threadIdx.x;
    if (i >= n) return;
    float x = p[3 * i + 0];
    float y = p[3 * i + 1];
    float z = p[3 * i + 2];
    g_pk[i] = make_float4(x, y, z, 0.0f);

    int ix = min(max((int)floorf((x - XMIN) * INVH), 0), G - 1);
    int iy = min(max((int)floorf((y - XMIN) * INVH), 0), G - 1);
    int iz = min(max((int)floorf((z - XMIN) * INVH), 0), G - 1);
    int cell = (iz * G + iy) * G + ix;

    g_qcell[i] = cell;
    g_qslot[i] = atomicAdd(&g_cnt[cell], 1);
}

// Warp-shuffle block scan over 256 cells.
__global__ void scan1_kernel() {
    __shared__ int wsum[8];
    int b = blockIdx.x, t = threadIdx.x;
    int lane = t & 31, w = t >> 5;
    int i = b * SCAN_B + t;
    int v = g_cnt[i];
    int x = v;
#pragma unroll
    for (int o = 1; o < 32; o <<= 1) {
        int y = __shfl_up_sync(0xffffffffu, x, o);
        if (lane >= o) x += y;
    }
    if (lane == 31) wsum[w] = x;
    __syncthreads();
    if (w == 0) {
        int s = (lane < 8) ? wsum[lane] : 0;
#pragma unroll
        for (int o = 1; o < 8; o <<= 1) {
            int y = __shfl_up_sync(0xffffffffu, s, o);
            if (lane >= o) s += y;
        }
        if (lane < 8) wsum[lane] = s;
    }
    __syncthreads();
    int off = (w > 0) ? wsum[w - 1] : 0;
    g_cexc[i] = off + x - v;
    if (t == SCAN_B - 1) g_bsum[b] = off + x;
}

// finalize: block b needs only sum(bsum[0..b-1]) — warp 0 computes it
// directly (<=4 loads/lane), then all threads write their cstart entries.
__global__ void finalize_kernel(int n) {
    __shared__ int s_off;
    int b = blockIdx.x, t = threadIdx.x;
    if (t < 32) {
        int acc = 0;
        for (int i = t; i < b; i += 32) acc += g_bsum[i];
#pragma unroll
        for (int o = 16; o > 0; o >>= 1)
            acc += __shfl_xor_sync(0xffffffffu, acc, o);
        if (t == 0) s_off = acc;
    }
    __syncthreads();
    int i = b * SCAN_B + t;
    g_cstart[i] = s_off + g_cexc[i];
    if (i == NC - 1) g_cstart[NC] = n;
}

__global__ void scatter_kernel(int n) {
    int i = blockIdx.x * blockDim.x + threadIdx.x;
    if (i >= n) return;
    int pos = g_cstart[g_qcell[i]] + g_qslot[i];
    float4 pk = g_pk[i];
    g_spts[pos] = make_float4(pk.x, pk.y, pk.z, __int_as_float(i));
}

// Warp-per-query grid search over cell-sorted points. Lanes set up row
// slices in parallel; nonempty rows are ballot-masked; in-ball hits
// ballot-compact into smem; top-11 by rank counting (order-invariant sum).
// Failures (undercount/overflow) go to the block-parallel repair kernel.
__global__ __launch_bounds__(QW * 32) void query_kernel(
    const float* __restrict__ W,
    const float* __restrict__ Bb,
    float* __restrict__ out,
    int n)
{
    __shared__ float4 s_cand[QW][CCAND];
    __shared__ float  s_d[QW][CCAND];

    int warp = threadIdx.x >> 5;
    int lane = threadIdx.x & 31;
    int t = blockIdx.x * QW + warp;
    if (t >= n) return;

    float4 me = g_spts[t];
    float qx = me.x, qy = me.y, qz = me.z;
    int   qi = __float_as_int(me.w);

    // Analytic seed threshold (11-NN radius from local Gaussian density).
    float q2 = qx * qx + qy * qy + qz * qz;
    float lam = (float)n * 0.063493636f * __expf(-0.5f * q2);
    float f = 2.6260608f / lam;
    float r2 = cbrtf(f * f);
    float seed = fminf((2.0f + 0.25f * q2) * r2, RADCAP2);
    float rad = sqrtf(seed);

    int y0 = min(max((int)floorf((qy - rad - XMIN) * INVH), 0), G - 1);
    int y1 = min(max((int)floorf((qy + rad - XMIN) * INVH), 0), G - 1);
    int z0 = min(max((int)floorf((qz - rad - XMIN) * INVH), 0), G - 1);
    int z1 = min(max((int)floorf((qz + rad - XMIN) * INVH), 0), G - 1);
    int nry = y1 - y0 + 1;
    int nrows = nry * (z1 - z0 + 1);

    int cnt = 0;

    for (int rb = 0; rb < nrows; rb += 32) {
        int r = rb + lane;
        bool valid = r < nrows;
        int st = 0, en = 0;
        if (valid) {
            int iz = z0 + r / nry;
            int iy = y0 + r % nry;
            float ylo = XMIN + iy * H;
            float zlo = XMIN + iz * H;
            float dy = fmaxf(fmaxf(ylo - qy, qy - (ylo + H)), 0.0f);
            float dz = fmaxf(fmaxf(zlo - qz, qz - (zlo + H)), 0.0f);
            float rem = seed - dy * dy - dz * dz;
            if (rem > 0.0f) {
                float hw = sqrtf(rem);
                int x0 = min(max((int)floorf((qx - hw - XMIN) * INVH), 0), G - 1);
                int x1 = min(max((int)floorf((qx + hw - XMIN) * INVH), 0), G - 1);
                int base = (iz * G + iy) * G;
                st = g_cstart[base + x0];
                en = g_cstart[base + x1 + 1];
            }
        }
        unsigned rowmask = __ballot_sync(0xffffffffu, en > st);
        while (rowmask) {
            int rr = __ffs(rowmask) - 1;
            rowmask &= rowmask - 1;
            int rst = __shfl_sync(0xffffffffu, st, rr);
            int ren = __shfl_sync(0xffffffffu, en, rr);
            for (int cb = rst; cb < ren; cb += 32) {
                int c = cb + lane;
                bool act = c < ren;
                float4 cd = act ? g_spts[c]
                                : make_float4(0.f, 0.f, 0.f, __int_as_float(-1));
                float dx = qx - cd.x;
                float dy = qy - cd.y;
                float dz = qz - cd.z;
                float d = fmaf(dz, dz, fmaf(dy, dy, dx * dx));
                bool keep = act && (d < seed) && (__float_as_int(cd.w) != qi);
                unsigned m = __ballot_sync(0xffffffffu, keep);
                int pos = cnt + __popc(m & ((1u << lane) - 1u));
                if (keep && pos < CCAND) {
                    s_cand[warp][pos] = cd;
                    s_d[warp][pos] = d;
                }
                cnt += __popc(m);
            }
        }
    }

    __syncwarp();

    if (cnt < KNN || cnt > CCAND) {
        if (lane == 0) {
            int slot = atomicAdd(&g_fail_cnt, 1);
            g_fail[slot] = qi;
        }
        return;
    }

    float w0 = W[0], w1 = W[1], w2 = W[2];

    // Rank selection: item i is a neighbor iff fewer than KNN items are
    // strictly smaller (ties broken by index). Sum is order-invariant.
    float Ssum = 0.0f;
    for (int i = lane; i < cnt; i += 32) {
        float di = s_d[warp][i];
        int rank = 0;
        for (int j = 0; j < cnt; j++) {
            float dj = s_d[warp][j];
            rank += (dj < di) || (dj == di && j < i);
        }
        if (rank < KNN) {
            float4 cd = s_cand[warp][i];
            Ssum += fabsf(qx - cd.x) * w0 + fabsf(qy - cd.y) * w1
                  + fabsf(qz - cd.z) * w2;
        }
    }
#pragma unroll
    for (int o = 16; o > 0; o >>= 1)
        Ssum += __shfl_xor_sync(0xffffffffu, Ssum, o);

    if (lane == 0) {
        float xw0 = qx * w0 + qy * w1 + qz * w2;
        const float inv_s2 = 0.7071067811865475f;
        const float c0f = (1.0f + (float)KNN * inv_s2) / 12.0f; // (1+11/sqrt2)/12
        const float c1f = 1.0f / 24.0f;                          // 0.5/12
        out[qi] = fmaf(c0f, xw0, fmaf(c1f, Ssum, Bb[0]));
    }
}

__device__ __forceinline__ void ins(float d, int j, float dist[KNN], int idxk[KNN]) {
    float dd = d; int jj = j;
#pragma unroll
    for (int k = 0; k < KNN; k++) {
        if (dd < dist[k]) {
            float td = dist[k]; int tj = idxk[k];
            dist[k] = dd; idxk[k] = jj;
            dd = td;      jj = tj;
        }
    }
}

// Exact repair: block-per-failed-query brute force with tournament merge.
__global__ __launch_bounds__(RTPB) void repair_kernel(
    const float* __restrict__ W,
    const float* __restrict__ Bb,
    float* __restrict__ out,
    int n)
{
    __shared__ float sd[RTPB * KNN];
    __shared__ int   si[RTPB * KNN];

    int tid = threadIdx.x;
    int nf = g_fail_cnt;

    for (int fq = blockIdx.x; fq < nf; fq += gridDim.x) {
        int qi = g_fail[fq];
        float4 q = g_pk[qi];
        float qx = q.x, qy = q.y, qz = q.z;

        float dist[KNN]; int idxk[KNN];
#pragma unroll
        for (int k = 0; k < KNN; k++) { dist[k] = 3.0e38f; idxk[k] = -1; }

        for (int j = tid; j < n; j += RTPB) {
            float4 c = g_pk[j];
            float dx = qx - c.x;
            float dy = qy - c.y;
            float dz = qz - c.z;
            float d = fmaf(dz, dz, fmaf(dy, dy, dx * dx));
            if (d < dist[KNN - 1] && j != qi) ins(d, j, dist, idxk);
        }
#pragma unroll
        for (int k = 0; k < KNN; k++) {
            sd[tid * KNN + k] = dist[k];
            si[tid * KNN + k] = idxk[k];
        }
        __syncthreads();

        for (int stride = RTPB / 2; stride >= 1; stride >>= 1) {
            if (tid < stride) {
                int prow = (tid + stride) * KNN;
#pragma unroll
                for (int k = 0; k < KNN; k++) {
                    float d = sd[prow + k];
                    if (d >= dist[KNN - 1]) break;
                    int j = si[prow + k];
                    if (j < 0) break;
                    ins(d, j, dist, idxk);
                }
            }
            __syncthreads();
            if (tid < stride) {
#pragma unroll
                for (int k = 0; k < KNN; k++) {
                    sd[tid * KNN + k] = dist[k];
                    si[tid * KNN + k] = idxk[k];
                }
            }
            __syncthreads();
        }

        if (tid == 0) {
            float w0 = W[0], w1 = W[1], w2 = W[2];
            float Ssum = 0.0f;
#pragma unroll
            for (int k = 0; k < KNN; k++) {
                float4 c = g_pk[idxk[k]];
                Ssum += fabsf(qx - c.x) * w0 + fabsf(qy - c.y) * w1
                      + fabsf(qz - c.z) * w2;
            }
            float xw0 = qx * w0 + qy * w1 + qz * w2;
            const float inv_s2 = 0.7071067811865475f;
            const float c0f = (1.0f + (float)KNN * inv_s2) / 12.0f;
            const float c1f = 1.0f / 24.0f;
            out[qi] = fmaf(c0f, xw0, fmaf(c1f, Ssum, Bb[0]));
        }
        __syncthreads();
    }
}

extern "C" void kernel_launch(void* const* d_in, const int* in_sizes, int n_in,
                              void* d_out, int out_size) {
    const float* p = (const float*)d_in[0];   // [2*8192*3] fp32
    const float* W = (const float*)d_in[1];   // [3]
    const float* b = (const float*)d_in[2];   // [1]
    float* out = (float*)d_out;               // [n,1] fp32

    int n = in_sizes[0] / 3;                  // 16384

    zero_kernel<<<(NC / 4 + 255) / 256, 256>>>();
    bin_kernel<<<(n + 255) / 256, 256>>>(p, n);
    scan1_kernel<<<NB1, SCAN_B>>>();
    finalize_kernel<<<NB1, SCAN_B>>>(n);
    scatter_kernel<<<(n + 255) / 256, 256>>>(n);
    query_kernel<<<(n + QW - 1) / QW, QW * 32>>>(W, b, out, n);
    repair_kernel<<<RGRID, RTPB>>>(W, b, out, n);
}